// round 2
// baseline (speedup 1.0000x reference)
#include <cuda_runtime.h>

// Output layout: out[b][o][gd][gh][gw], o = ((pd*4+ph)*4+pw)*12 + v
// B=2, V=12, P=4, D=H=W=128, Gd=Gh=Gw=32, out_dim=768.
// Input voxel: x[b][gd*4+pd][gh*4+ph][gw*4+pw]
// bin = searchsorted(HU_EDGES, x, 'right') = sum(x >= edge_i), 9 edges.

__global__ __launch_bounds__(256) void lcv_kernel(
    const float* __restrict__ x,
    const float* __restrict__ vectors,
    float* __restrict__ out,
    int n4)
{
    __shared__ float vs[120];  // 10 bins x 12 dims
    if (threadIdx.x < 120) vs[threadIdx.x] = vectors[threadIdx.x];
    __syncthreads();

    int vidx = blockIdx.x * blockDim.x + threadIdx.x;
    if (vidx >= n4) return;

    // vidx indexes float4 units of output: [b][o][gd][gh][gw4], gw4 in [0,8)
    int gw4 = vidx & 7;
    int t   = vidx >> 3;
    int gh  = t & 31; t >>= 5;
    int gd  = t & 31; t >>= 5;
    int b   = (t >= 768) ? 1 : 0;
    int o   = t - b * 768;

    int p  = o / 12;          // patch-voxel index 0..63
    int v  = o - p * 12;      // vector dim 0..11
    int pw = p & 3;
    int ph = (p >> 2) & 3;
    int pd = p >> 4;

    int d = gd * 4 + pd;
    int h = gh * 4 + ph;
    // base w for k=0: gw = gw4*4 + k, w = gw*4 + pw
    const float* xr = x + ((((long long)b * 128 + d) * 128 + h) * 128
                           + gw4 * 16 + pw);

    float4 r;
    float* rp = &r.x;
    #pragma unroll
    for (int k = 0; k < 4; k++) {
        float xv = __ldg(xr + k * 4);
        int bin = (xv >= -1000.0f) + (xv >= -75.0f) + (xv >= 0.0f)
                + (xv >= 15.0f)    + (xv >= 25.0f)  + (xv >= 40.0f)
                + (xv >= 50.0f)    + (xv >= 200.0f) + (xv >= 1000.0f);
        rp[k] = vs[bin * 12 + v];
    }
    reinterpret_cast<float4*>(out)[vidx] = r;
}

extern "C" void kernel_launch(void* const* d_in, const int* in_sizes, int n_in,
                              void* d_out, int out_size)
{
    const float* x       = (const float*)d_in[0];
    const float* vectors = (const float*)d_in[1];
    float* out           = (float*)d_out;

    int n4 = out_size / 4;                 // 12,582,912 float4 stores
    int threads = 256;
    int blocks = (n4 + threads - 1) / threads;
    lcv_kernel<<<blocks, threads>>>(x, vectors, out, n4);
}

// round 3
// speedup vs baseline: 2.7409x; 2.7409x over previous
#include <cuda_runtime.h>

// x: (2,1,128,128,128) f32; vectors: (10,12) f32
// out: (2, 768, 32, 32, 32) f32, o = ((pd*4+ph)*4+pw)*12 + v
// bin = searchsorted(HU_EDGES, x, 'right') = sum(x >= edge_i)
//
// One block per (b, gd, gh): 2048 blocks, 256 threads.
// Phase 1: coalesced load of 4x4x128 x-slab, bins packed 4/uint32 in smem.
// Phase 2: 24 iters/thread, each: LDS.128 of 4 bin-words, 4 table lookups,
//          one coalesced float4 store.

__global__ __launch_bounds__(256) void lcv_kernel(
    const float* __restrict__ x,
    const float* __restrict__ vectors,
    float* __restrict__ out)
{
    __shared__ float vs[120];          // 10 bins x 12 dims
    __shared__ unsigned int sbin[512]; // [pd][ph][wq] : 4 bins packed per word

    const int tid = threadIdx.x;
    if (tid < 120) vs[tid] = vectors[tid];

    const int bi = blockIdx.x;
    const int gh = bi & 31;
    const int gd = (bi >> 5) & 31;
    const int b  = bi >> 10;

    // ---- Phase 1: bins for the 4x4x128 slab (2048 voxels, 512 packed words)
    #pragma unroll
    for (int j = tid; j < 512; j += 256) {
        int wq = j & 31;           // which float4 along w
        int ph = (j >> 5) & 3;
        int pd = j >> 7;
        long long xoff = (((long long)b * 128 + (gd * 4 + pd)) * 128
                          + (gh * 4 + ph)) * 128 + wq * 4;
        float4 xv = *reinterpret_cast<const float4*>(x + xoff);
        const float* xp = &xv.x;
        unsigned int packed = 0;
        #pragma unroll
        for (int q = 0; q < 4; q++) {
            float f = xp[q];
            unsigned int bin =
                  (f >= -1000.0f) + (f >= -75.0f) + (f >= 0.0f)
                + (f >= 15.0f)    + (f >= 25.0f)  + (f >= 40.0f)
                + (f >= 50.0f)    + (f >= 200.0f) + (f >= 1000.0f);
            packed |= bin << (q * 8);
        }
        sbin[j] = packed;
    }
    __syncthreads();

    // ---- Phase 2: 768*8 = 6144 float4 outputs per block, 24 per thread
    const uint4* sbin4 = reinterpret_cast<const uint4*>(sbin); // [4][4][8]
    const int gw4 = tid & 7;
    int o = tid >> 3;                  // starts in [0,32), step 32
    int p = o / 12;
    int v = o - p * 12;

    float4* out4 = reinterpret_cast<float4*>(out);
    const long long base = (long long)b * 768 * 8192
                         + (gd * 32 + gh) * 8 + gw4;

    #pragma unroll
    for (int it = 0; it < 24; it++) {
        int pw = p & 3;
        int ph = (p >> 2) & 3;
        int pd = p >> 4;
        uint4 wv = sbin4[(pd * 4 + ph) * 8 + gw4];
        int sh = pw * 8;
        float4 r;
        r.x = vs[((wv.x >> sh) & 0xFF) * 12 + v];
        r.y = vs[((wv.y >> sh) & 0xFF) * 12 + v];
        r.z = vs[((wv.z >> sh) & 0xFF) * 12 + v];
        r.w = vs[((wv.w >> sh) & 0xFF) * 12 + v];
        out4[base + (long long)o * 8192] = r;

        o += 32;
        v += 8; p += 2;
        if (v >= 12) { v -= 12; p += 1; }
    }
}

extern "C" void kernel_launch(void* const* d_in, const int* in_sizes, int n_in,
                              void* d_out, int out_size)
{
    const float* x       = (const float*)d_in[0];
    const float* vectors = (const float*)d_in[1];
    float* out           = (float*)d_out;
    lcv_kernel<<<2048, 256>>>(x, vectors, out);
}

// round 4
// speedup vs baseline: 3.0733x; 1.1213x over previous
#include <cuda_runtime.h>

// x: (2,1,128,128,128) f32; vectors: (10,12) f32
// out: (2, 768, 32, 32, 32) f32, o = ((pd*4+ph)*4+pw)*12 + v
// bin = searchsorted(HU_EDGES, x, 'right') = sum(x >= edge_i)
//
// grid = 2048 blocks (b,gd,gh), block = 128 threads (pd,ph,gw4).
// Each thread: 4x LDG.128 -> 16 bins in 4 packed regs -> 48 float4 stores.

__device__ __forceinline__ unsigned int bin4(float4 xv)
{
    const float* xp = &xv.x;
    unsigned int packed = 0;
    #pragma unroll
    for (int q = 0; q < 4; q++) {
        float f = xp[q];
        unsigned int bin =
              (f >= -1000.0f) + (f >= -75.0f) + (f >= 0.0f)
            + (f >= 15.0f)    + (f >= 25.0f)  + (f >= 40.0f)
            + (f >= 50.0f)    + (f >= 200.0f) + (f >= 1000.0f);
        packed |= bin << (q * 8);
    }
    return packed;
}

__global__ __launch_bounds__(128) void lcv_kernel(
    const float* __restrict__ x,
    const float* __restrict__ vectors,
    float* __restrict__ out)
{
    __shared__ float vs[120];          // 10 bins x 12 dims
    const int tid = threadIdx.x;
    if (tid < 120) vs[tid] = vectors[tid];
    __syncthreads();

    const int gw4 = tid & 7;
    const int ph  = (tid >> 3) & 3;
    const int pd  = tid >> 5;

    const int bi = blockIdx.x;
    const int gh = bi & 31;
    const int gd = (bi >> 5) & 31;
    const int b  = bi >> 10;

    // ---- load 16 x values for this thread's column
    const long long xoff = (((long long)b * 128 + (gd * 4 + pd)) * 128
                            + (gh * 4 + ph)) * 128 + gw4 * 16;
    const float4* xr = reinterpret_cast<const float4*>(x + xoff);
    // word k holds bins of voxels w = gw4*16 + 4k + {0..3}; byte pw selects
    // the voxel entering output lane gw = gw4*4 + k.
    unsigned int w0 = bin4(__ldg(xr + 0));
    unsigned int w1 = bin4(__ldg(xr + 1));
    unsigned int w2 = bin4(__ldg(xr + 2));
    unsigned int w3 = bin4(__ldg(xr + 3));

    float4* out4 = reinterpret_cast<float4*>(out);
    const long long base = (long long)b * 768 * 8192
                         + (gd * 32 + gh) * 8 + gw4;
    const int p_hi = (pd * 4 + ph) * 4;   // p = p_hi + pw

    #pragma unroll
    for (int pw = 0; pw < 4; pw++) {
        const int sh = pw * 8;
        const float* p0 = vs + ((w0 >> sh) & 0xFF) * 12;
        const float* p1 = vs + ((w1 >> sh) & 0xFF) * 12;
        const float* p2 = vs + ((w2 >> sh) & 0xFF) * 12;
        const float* p3 = vs + ((w3 >> sh) & 0xFF) * 12;
        long long obase = base + (long long)(p_hi + pw) * 12 * 8192;
        #pragma unroll
        for (int v = 0; v < 12; v++) {
            float4 r;
            r.x = p0[v]; r.y = p1[v]; r.z = p2[v]; r.w = p3[v];
            __stcs(&out4[obase + (long long)v * 8192], r);
        }
    }
}

extern "C" void kernel_launch(void* const* d_in, const int* in_sizes, int n_in,
                              void* d_out, int out_size)
{
    const float* x       = (const float*)d_in[0];
    const float* vectors = (const float*)d_in[1];
    float* out           = (float*)d_out;
    lcv_kernel<<<2048, 128>>>(x, vectors, out);
}

// round 6
// speedup vs baseline: 3.1014x; 1.0091x over previous
#include <cuda_runtime.h>

// x: (2,1,128,128,128) f32; vectors: (10,12) f32
// out: (2, 768, 32, 32, 32) f32, o = ((pd*4+ph)*4+pw)*12 + v
// bin = searchsorted(HU_EDGES, x, 'right') = sum(x >= edge_i)
//
// grid = 2048 blocks (b,gd,gh), block = 512 threads (pd,ph,pw,gw4).
// Each thread: 4 scalar LDG -> 4 bins -> 12 coalesced float4 stores.

__device__ __forceinline__ int bin1(float f)
{
    return (f >= -1000.0f) + (f >= -75.0f) + (f >= 0.0f)
         + (f >= 15.0f)    + (f >= 25.0f)  + (f >= 40.0f)
         + (f >= 50.0f)    + (f >= 200.0f) + (f >= 1000.0f);
}

__global__ __launch_bounds__(512) void lcv_kernel(
    const float* __restrict__ x,
    const float* __restrict__ vectors,
    float* __restrict__ out)
{
    __shared__ float vs[120];          // 10 bins x 12 dims
    const int tid = threadIdx.x;
    if (tid < 120) vs[tid] = vectors[tid];
    __syncthreads();

    const int gw4 = tid & 7;
    const int pw  = (tid >> 3) & 3;
    const int ph  = (tid >> 5) & 3;
    const int pd  = tid >> 7;

    const int bi = blockIdx.x;
    const int gh = bi & 31;
    const int gd = (bi >> 5) & 31;
    const int b  = bi >> 10;

    // voxels this thread needs: w = gw4*16 + 4k + pw, k = 0..3
    const long long xoff = (((long long)b * 128 + (gd * 4 + pd)) * 128
                            + (gh * 4 + ph)) * 128 + gw4 * 16 + pw;
    const float* xr = x + xoff;
    const float* p0 = vs + bin1(__ldg(xr + 0))  * 12;
    const float* p1 = vs + bin1(__ldg(xr + 4))  * 12;
    const float* p2 = vs + bin1(__ldg(xr + 8))  * 12;
    const float* p3 = vs + bin1(__ldg(xr + 12)) * 12;

    float4* out4 = reinterpret_cast<float4*>(out);
    const int p = (pd * 4 + ph) * 4 + pw;
    const long long obase = (long long)b * 768 * 8192
                          + (long long)p * 12 * 8192
                          + (gd * 32 + gh) * 8 + gw4;

    #pragma unroll
    for (int v = 0; v < 12; v++) {
        float4 r;
        r.x = p0[v]; r.y = p1[v]; r.z = p2[v]; r.w = p3[v];
        __stcs(&out4[obase + (long long)v * 8192], r);
    }
}

extern "C" void kernel_launch(void* const* d_in, const int* in_sizes, int n_in,
                              void* d_out, int out_size)
{
    const float* x       = (const float*)d_in[0];
    const float* vectors = (const float*)d_in[1];
    float* out           = (float*)d_out;
    lcv_kernel<<<2048, 512>>>(x, vectors, out);
}